// round 13
// baseline (speedup 1.0000x reference)
#include <cuda_runtime.h>

#define NN   100000
#define EE   1600000
#define EAA  1000000
#define GG   512
#define F_INN 16
#define HH   32
#define SLOTS 96

// ---- scratch (device globals) ----
__device__ __align__(16) float g_deg[NN];          // dinv
__device__ __align__(16) float g_y  [NN * HH];     // layer-1 gather source (y1)
__device__ __align__(16) float g_y2 [NN * HH];     // layer-2 gather source (y2)
__device__ __align__(16) float g_h  [NN * HH];     // layer-2 output (edge head)
__device__ __align__(16) float g_u  [NN * HH];     // h @ Wbil
__device__ __align__(16) float g_pooled[GG * HH];
__device__ float g_cnt[GG];
__device__ int   g_cnt_i[NN];                      // in-degree (no self loop)
__device__ int   g_slot[NN * SLOTS];               // src ids, fixed stride per dst

// ---------------- build kernels (round-10 proven) ----------------

__global__ void k_zero() {
    int i = blockIdx.x * blockDim.x + threadIdx.x;
    if (i < NN)      g_cnt_i[i] = 0;
    if (i < GG * HH) g_pooled[i] = 0.f;
    if (i < GG)      g_cnt[i] = 0.f;
}

__global__ void k_fillslot(const int* __restrict__ src, const int* __restrict__ dst) {
    int e = blockIdx.x * blockDim.x + threadIdx.x;
    if (e >= EE) return;
    int d = dst[e];
    int slot = atomicAdd(&g_cnt_i[d], 1);
    g_slot[d * SLOTS + slot] = src[e];
}

__global__ void k_dinv() {
    int i = blockIdx.x * blockDim.x + threadIdx.x;
    if (i < NN) g_deg[i] = rsqrtf((float)g_cnt_i[i] + 1.0f);
}

// ---------------- compute kernels ----------------

// y1 = (x @ W1) * dinv ; 4 threads per node (round-10 proven)
__global__ void k_mm1(const float* __restrict__ x, const float* __restrict__ W1) {
    __shared__ float sW[F_INN * HH];
    for (int i = threadIdx.x; i < F_INN * HH; i += blockDim.x) sW[i] = W1[i];
    __syncthreads();
    int t = blockIdx.x * blockDim.x + threadIdx.x;
    int node = t >> 2, q = t & 3;
    if (node >= NN) return;
    float acc[8];
#pragma unroll
    for (int j = 0; j < 8; j++) acc[j] = 0.f;
    const float4* xr = reinterpret_cast<const float4*>(x + node * F_INN);
#pragma unroll
    for (int kk = 0; kk < F_INN / 4; kk++) {
        float4 xv = xr[kk];
        float xs[4] = {xv.x, xv.y, xv.z, xv.w};
#pragma unroll
        for (int p = 0; p < 4; p++) {
            int k = kk * 4 + p;
#pragma unroll
            for (int j = 0; j < 8; j++)
                acc[j] = fmaf(xs[p], sW[k * HH + q * 8 + j], acc[j]);
        }
    }
    float dv = g_deg[node];
    int o = node * 8 + q * 2;
    reinterpret_cast<float4*>(g_y)[o]     = make_float4(acc[0]*dv, acc[1]*dv, acc[2]*dv, acc[3]*dv);
    reinterpret_cast<float4*>(g_y)[o + 1] = make_float4(acc[4]*dv, acc[5]*dv, acc[6]*dv, acc[7]*dv);
}

// warp-per-node gather: lane = (sub, c); sub strides the slot list by 4,
// c indexes the float4 chunk. Returns per-lane partial; after the
// shuffle-reduce lanes 0..7 (sub==0) hold the full chunk sums.
__device__ __forceinline__ float4 gather_warp(const float4* __restrict__ y4,
                                              int node, int sub, int c) {
    float4 acc = make_float4(0.f, 0.f, 0.f, 0.f);
    if (sub == 0) acc = y4[node * 8 + c];          // self-loop term
    float4 acc2 = make_float4(0.f, 0.f, 0.f, 0.f);
    int m = g_cnt_i[node];
    int base = node * SLOTS;
    int i = sub;
    for (; i + 4 < m; i += 8) {                    // 2 independent loads/iter
        int s0 = g_slot[base + i];
        int s1 = g_slot[base + i + 4];
        float4 v0 = y4[s0 * 8 + c];
        float4 v1 = y4[s1 * 8 + c];
        acc.x  += v0.x; acc.y  += v0.y; acc.z  += v0.z; acc.w  += v0.w;
        acc2.x += v1.x; acc2.y += v1.y; acc2.z += v1.z; acc2.w += v1.w;
    }
    if (i < m) {
        float4 v = y4[g_slot[base + i] * 8 + c];
        acc.x += v.x; acc.y += v.y; acc.z += v.z; acc.w += v.w;
    }
    acc.x += acc2.x; acc.y += acc2.y; acc.z += acc2.z; acc.w += acc2.w;
    // reduce across sub (lanes 8/16/24 fold into 0..7)
    acc.x += __shfl_down_sync(0xffffffffu, acc.x, 16);
    acc.y += __shfl_down_sync(0xffffffffu, acc.y, 16);
    acc.z += __shfl_down_sync(0xffffffffu, acc.z, 16);
    acc.w += __shfl_down_sync(0xffffffffu, acc.w, 16);
    acc.x += __shfl_down_sync(0xffffffffu, acc.x, 8);
    acc.y += __shfl_down_sync(0xffffffffu, acc.y, 8);
    acc.z += __shfl_down_sync(0xffffffffu, acc.z, 8);
    acc.w += __shfl_down_sync(0xffffffffu, acc.w, 8);
    return acc;
}

#define WNODES 8      // warps (=nodes) per block
#define HPAD 36

// fused: warp-gather of y1 + relu epilogue (smem) + @W2 matmul -> y2 (*dinv)
__global__ void k_gmm(const float* __restrict__ b1, const float* __restrict__ W2) {
    __shared__ float sW[HH * HH];
    __shared__ float sb[HH];
    __shared__ float sh[WNODES * HPAD];
    for (int i = threadIdx.x; i < HH * HH; i += blockDim.x) sW[i] = W2[i];
    if (threadIdx.x < HH) sb[threadIdx.x] = b1[threadIdx.x];
    __syncthreads();

    int lane = threadIdx.x & 31;
    int w    = threadIdx.x >> 5;
    int node = blockIdx.x * WNODES + w;
    int sub = lane >> 3, c = lane & 7;
    bool ok = node < NN;                 // warp-uniform

    if (ok) {
        const float4* y4 = reinterpret_cast<const float4*>(g_y);
        float4 acc = gather_warp(y4, node, sub, c);
        if (sub == 0) {
            float dv = g_deg[node];
            float* hr = sh + w * HPAD + c * 4;
            hr[0] = fmaxf(acc.x * dv + sb[c*4+0], 0.f);
            hr[1] = fmaxf(acc.y * dv + sb[c*4+1], 0.f);
            hr[2] = fmaxf(acc.z * dv + sb[c*4+2], 0.f);
            hr[3] = fmaxf(acc.w * dv + sb[c*4+3], 0.f);
        }
    }
    __syncthreads();
    if (!ok) return;

    // warp-per-node matmul: lane = output column, hrow reads broadcast
    float a = 0.f;
    const float* hrow = sh + w * HPAD;
#pragma unroll
    for (int k = 0; k < HH; k++) a = fmaf(hrow[k], sW[k * HH + lane], a);
    g_y2[node * HH + lane] = a * g_deg[node];
}

// fused: warp-gather of y2 + epilogue -> g_h, pooling, u = h2 @ Wbil -> g_u
__global__ void k_ghead(const float* __restrict__ b2, const float* __restrict__ Wbil,
                        const int* __restrict__ batch) {
    __shared__ float sW[HH * HH];
    __shared__ float sb[HH];
    __shared__ float sh[WNODES * HPAD];
    for (int i = threadIdx.x; i < HH * HH; i += blockDim.x) sW[i] = Wbil[i];
    if (threadIdx.x < HH) sb[threadIdx.x] = b2[threadIdx.x];
    __syncthreads();

    int lane = threadIdx.x & 31;
    int w    = threadIdx.x >> 5;
    int node = blockIdx.x * WNODES + w;
    int sub = lane >> 3, c = lane & 7;
    bool ok = node < NN;

    if (ok) {
        const float4* y4 = reinterpret_cast<const float4*>(g_y2);
        float4 acc = gather_warp(y4, node, sub, c);
        if (sub == 0) {
            float dv = g_deg[node];
            float4 h2;
            h2.x = acc.x * dv + sb[c*4+0];
            h2.y = acc.y * dv + sb[c*4+1];
            h2.z = acc.z * dv + sb[c*4+2];
            h2.w = acc.w * dv + sb[c*4+3];
            float* hr = sh + w * HPAD + c * 4;
            hr[0] = h2.x; hr[1] = h2.y; hr[2] = h2.z; hr[3] = h2.w;
            reinterpret_cast<float4*>(g_h)[node * 8 + c] = h2;
            int g = batch[node];
            atomicAdd(reinterpret_cast<float4*>(g_pooled) + g * 8 + c, h2);
            if (c == 0) atomicAdd(&g_cnt[g], 1.0f);
        }
    }
    __syncthreads();
    if (!ok) return;

    float a = 0.f;
    const float* hrow = sh + w * HPAD;
#pragma unroll
    for (int k = 0; k < HH; k++) a = fmaf(hrow[k], sW[k * HH + lane], a);
    g_u[node * HH + lane] = a;
}

// edge head (4 threads/edge, 2x float4 per operand) + fused reg head in last block
__global__ void k_edge(const int* __restrict__ asrc, const int* __restrict__ adst,
                       const float* __restrict__ bbil,
                       const float* __restrict__ Wr, const float* __restrict__ br,
                       float* __restrict__ out) {
    if (blockIdx.x == gridDim.x - 1) {
        for (int g = threadIdx.x; g < GG; g += 256) {
            float c = g_cnt[g];
            c = c < 1.f ? 1.f : c;
            float acc = 0.f;
#pragma unroll
            for (int h = 0; h < HH; h++) acc = fmaf(g_pooled[g * HH + h], Wr[h], acc);
            out[g] = acc / c + br[0];
        }
        return;
    }
    long t = (long)blockIdx.x * 256 + threadIdx.x;
    int e = (int)(t >> 2), lane = (int)(t & 3);
    if (e >= EAA) return;
    int s = asrc[e], d = adst[e];
    const float4* u4 = reinterpret_cast<const float4*>(g_u);
    const float4* h4 = reinterpret_cast<const float4*>(g_h);
    float4 a0 = u4[s * 8 + lane];
    float4 b0 = h4[d * 8 + lane];
    float4 a1 = u4[s * 8 + lane + 4];
    float4 b1 = h4[d * 8 + lane + 4];
    float p = a0.x*b0.x + a0.y*b0.y + a0.z*b0.z + a0.w*b0.w
            + a1.x*b1.x + a1.y*b1.y + a1.z*b1.z + a1.w*b1.w;
    p += __shfl_down_sync(0xffffffffu, p, 2, 4);
    p += __shfl_down_sync(0xffffffffu, p, 1, 4);
    if (lane == 0) out[GG + e] = p + bbil[0];
}

// ---------------- launch ----------------

extern "C" void kernel_launch(void* const* d_in, const int* in_sizes, int n_in,
                              void* d_out, int out_size) {
    const float* x    = (const float*)d_in[0];
    const int*   ei   = (const int*)  d_in[1];
    const int*   eia  = (const int*)  d_in[2];
    const int*   batch= (const int*)  d_in[3];
    const float* W1   = (const float*)d_in[4];
    const float* b1   = (const float*)d_in[5];
    const float* W2   = (const float*)d_in[6];
    const float* b2   = (const float*)d_in[7];
    const float* Wr   = (const float*)d_in[8];
    const float* br   = (const float*)d_in[9];
    const float* Wbil = (const float*)d_in[10];
    const float* bbil = (const float*)d_in[11];
    float* out = (float*)d_out;

    const int* src  = ei;
    const int* dst  = ei + EE;
    const int* asrc = eia;
    const int* adst = eia + EAA;

    const int B = 256;

    // one-pass slot build (round-10 proven)
    k_zero    <<<(NN + B - 1) / B, B>>>();
    k_fillslot<<<(EE + B - 1) / B, B>>>(src, dst);
    k_dinv    <<<(NN + B - 1) / B, B>>>();

    // layer 1 matmul, then fused warp-gather+relu+layer2 matmul (y1 -> y2)
    k_mm1  <<<(NN * 4 + B - 1) / B, B>>>(x, W1);
    k_gmm  <<<(NN + WNODES - 1) / WNODES, B>>>(b1, W2);

    // fused warp-gather(y2) + epilogue + pooling + bilinear precompute
    k_ghead<<<(NN + WNODES - 1) / WNODES, B>>>(b2, Wbil, batch);

    // edge head + fused reg head
    int edge_blocks = (int)(((long)EAA * 4 + B - 1) / B);
    k_edge <<<edge_blocks + 1, B>>>(asrc, adst, bbil, Wr, br, out);
}

// round 14
// speedup vs baseline: 1.2210x; 1.2210x over previous
#include <cuda_runtime.h>

#define NN   100000
#define EE   1600000
#define EAA  1000000
#define GG   512
#define F_INN 16
#define HH   32
#define SLOTS 96

// ---- scratch (device globals) ----
__device__ __align__(16) float g_deg[NN];          // dinv
__device__ __align__(16) float g_y  [NN * HH];     // layer-1 gather source (y1)
__device__ __align__(16) float g_y2 [NN * HH];     // layer-2 gather source (y2)
__device__ __align__(16) float g_h  [NN * HH];     // layer-2 output (edge head)
__device__ __align__(16) float g_u  [NN * HH];     // h @ Wbil
__device__ __align__(16) float g_pooled[GG * HH];
__device__ float g_cnt[GG];
__device__ int   g_cnt_i[NN];                      // in-degree (no self loop)
__device__ __align__(16) int g_slot[NN * SLOTS];   // src ids, fixed stride per dst

// ---------------- build kernels (round-10 proven) ----------------

__global__ void k_zero() {
    int i = blockIdx.x * blockDim.x + threadIdx.x;
    if (i < NN)      g_cnt_i[i] = 0;
    if (i < GG * HH) g_pooled[i] = 0.f;
    if (i < GG)      g_cnt[i] = 0.f;
}

__global__ void k_fillslot(const int* __restrict__ src, const int* __restrict__ dst) {
    int e = blockIdx.x * blockDim.x + threadIdx.x;
    if (e >= EE) return;
    int d = dst[e];
    int slot = atomicAdd(&g_cnt_i[d], 1);
    g_slot[d * SLOTS + slot] = src[e];
}

__global__ void k_dinv() {
    int i = blockIdx.x * blockDim.x + threadIdx.x;
    if (i < NN) g_deg[i] = rsqrtf((float)g_cnt_i[i] + 1.0f);
}

// ---------------- compute kernels ----------------

// y1 = (x @ W1) * dinv ; 4 threads per node (round-10 proven)
__global__ void k_mm1(const float* __restrict__ x, const float* __restrict__ W1) {
    __shared__ float sW[F_INN * HH];
    for (int i = threadIdx.x; i < F_INN * HH; i += blockDim.x) sW[i] = W1[i];
    __syncthreads();
    int t = blockIdx.x * blockDim.x + threadIdx.x;
    int node = t >> 2, q = t & 3;
    if (node >= NN) return;
    float acc[8];
#pragma unroll
    for (int j = 0; j < 8; j++) acc[j] = 0.f;
    const float4* xr = reinterpret_cast<const float4*>(x + node * F_INN);
#pragma unroll
    for (int kk = 0; kk < F_INN / 4; kk++) {
        float4 xv = xr[kk];
        float xs[4] = {xv.x, xv.y, xv.z, xv.w};
#pragma unroll
        for (int p = 0; p < 4; p++) {
            int k = kk * 4 + p;
#pragma unroll
            for (int j = 0; j < 8; j++)
                acc[j] = fmaf(xs[p], sW[k * HH + q * 8 + j], acc[j]);
        }
    }
    float dv = g_deg[node];
    int o = node * 8 + q * 2;
    reinterpret_cast<float4*>(g_y)[o]     = make_float4(acc[0]*dv, acc[1]*dv, acc[2]*dv, acc[3]*dv);
    reinterpret_cast<float4*>(g_y)[o + 1] = make_float4(acc[4]*dv, acc[5]*dv, acc[6]*dv, acc[7]*dv);
}

// gather helper: int4 index loads (4 indices per LDG) + 4 outstanding row loads
__device__ __forceinline__ float4 gather_rows(const float4* __restrict__ y4,
                                              int base, int m, int c, float4 acc) {
    const int4* slot4 = reinterpret_cast<const int4*>(g_slot + base);
    float4 acc2 = make_float4(0.f, 0.f, 0.f, 0.f);
    int i = 0;
    for (; i + 4 <= m; i += 4) {
        int4 s = slot4[i >> 2];
        float4 v0 = y4[s.x * 8 + c];
        float4 v1 = y4[s.y * 8 + c];
        float4 v2 = y4[s.z * 8 + c];
        float4 v3 = y4[s.w * 8 + c];
        acc.x  += v0.x + v1.x; acc.y  += v0.y + v1.y;
        acc.z  += v0.z + v1.z; acc.w  += v0.w + v1.w;
        acc2.x += v2.x + v3.x; acc2.y += v2.y + v3.y;
        acc2.z += v2.z + v3.z; acc2.w += v2.w + v3.w;
    }
    for (; i < m; i++) {
        float4 v = y4[g_slot[base + i] * 8 + c];
        acc.x += v.x; acc.y += v.y; acc.z += v.z; acc.w += v.w;
    }
    acc.x += acc2.x; acc.y += acc2.y; acc.z += acc2.z; acc.w += acc2.w;
    return acc;
}

// fused: slot gather of y1 + relu epilogue (smem) + @W2 matmul -> y2 (*dinv)
#define NODES_PER_BLK 32
#define HPAD 36
__global__ void k_gmm(const float* __restrict__ b1, const float* __restrict__ W2) {
    __shared__ float sW[HH * HH];
    __shared__ float sb[HH];
    __shared__ float sh[NODES_PER_BLK * HPAD];
    for (int i = threadIdx.x; i < HH * HH; i += blockDim.x) sW[i] = W2[i];
    if (threadIdx.x < HH) sb[threadIdx.x] = b1[threadIdx.x];
    __syncthreads();

    int tid = threadIdx.x;
    int nl = tid >> 3, c = tid & 7;
    int node = blockIdx.x * NODES_PER_BLK + nl;
    bool ok = node < NN;

    if (ok) {
        int base = node * SLOTS;
        int m    = g_cnt_i[node];
        const float4* y4 = reinterpret_cast<const float4*>(g_y);
        float4 acc = gather_rows(y4, base, m, c, y4[node * 8 + c]);
        float dv = g_deg[node];
        float* hr = sh + nl * HPAD + c * 4;
        hr[0] = fmaxf(acc.x * dv + sb[c*4+0], 0.f);
        hr[1] = fmaxf(acc.y * dv + sb[c*4+1], 0.f);
        hr[2] = fmaxf(acc.z * dv + sb[c*4+2], 0.f);
        hr[3] = fmaxf(acc.w * dv + sb[c*4+3], 0.f);
    }
    __syncthreads();
    if (!ok) return;

    float a0 = 0.f, a1 = 0.f, a2 = 0.f, a3 = 0.f;
    const float* hrow = sh + nl * HPAD;
#pragma unroll
    for (int k = 0; k < HH; k++) {
        float hv = hrow[k];
        a0 = fmaf(hv, sW[k * HH + c * 4 + 0], a0);
        a1 = fmaf(hv, sW[k * HH + c * 4 + 1], a1);
        a2 = fmaf(hv, sW[k * HH + c * 4 + 2], a2);
        a3 = fmaf(hv, sW[k * HH + c * 4 + 3], a3);
    }
    float dv = g_deg[node];
    reinterpret_cast<float4*>(g_y2)[node * 8 + c] =
        make_float4(a0 * dv, a1 * dv, a2 * dv, a3 * dv);
}

// fused: slot gather of y2 + epilogue -> g_h, pooling, u = h2 @ Wbil -> g_u
__global__ void k_ghead(const float* __restrict__ b2, const float* __restrict__ Wbil,
                        const int* __restrict__ batch) {
    __shared__ float sW[HH * HH];
    __shared__ float sb[HH];
    __shared__ float sh[NODES_PER_BLK * HPAD];
    for (int i = threadIdx.x; i < HH * HH; i += blockDim.x) sW[i] = Wbil[i];
    if (threadIdx.x < HH) sb[threadIdx.x] = b2[threadIdx.x];
    __syncthreads();

    int tid = threadIdx.x;
    int nl = tid >> 3, c = tid & 7;
    int node = blockIdx.x * NODES_PER_BLK + nl;
    bool ok = node < NN;

    if (ok) {
        int base = node * SLOTS;
        int m    = g_cnt_i[node];
        const float4* y4 = reinterpret_cast<const float4*>(g_y2);
        float4 acc = gather_rows(y4, base, m, c, y4[node * 8 + c]);
        float dv = g_deg[node];
        float4 h2;
        h2.x = acc.x * dv + sb[c*4+0];
        h2.y = acc.y * dv + sb[c*4+1];
        h2.z = acc.z * dv + sb[c*4+2];
        h2.w = acc.w * dv + sb[c*4+3];
        float* hr = sh + nl * HPAD + c * 4;
        hr[0] = h2.x; hr[1] = h2.y; hr[2] = h2.z; hr[3] = h2.w;
        reinterpret_cast<float4*>(g_h)[node * 8 + c] = h2;
        int g = batch[node];
        atomicAdd(reinterpret_cast<float4*>(g_pooled) + g * 8 + c, h2);
        if (c == 0) atomicAdd(&g_cnt[g], 1.0f);
    }
    __syncthreads();
    if (!ok) return;

    float a0 = 0.f, a1 = 0.f, a2 = 0.f, a3 = 0.f;
    const float* hrow = sh + nl * HPAD;
#pragma unroll
    for (int k = 0; k < HH; k++) {
        float hv = hrow[k];
        a0 = fmaf(hv, sW[k * HH + c * 4 + 0], a0);
        a1 = fmaf(hv, sW[k * HH + c * 4 + 1], a1);
        a2 = fmaf(hv, sW[k * HH + c * 4 + 2], a2);
        a3 = fmaf(hv, sW[k * HH + c * 4 + 3], a3);
    }
    reinterpret_cast<float4*>(g_u)[node * 8 + c] = make_float4(a0, a1, a2, a3);
}

// edge head (4 threads/edge, 2x float4 per operand) + fused reg head in last block
__global__ void k_edge(const int* __restrict__ asrc, const int* __restrict__ adst,
                       const float* __restrict__ bbil,
                       const float* __restrict__ Wr, const float* __restrict__ br,
                       float* __restrict__ out) {
    if (blockIdx.x == gridDim.x - 1) {
        for (int g = threadIdx.x; g < GG; g += 256) {
            float c = g_cnt[g];
            c = c < 1.f ? 1.f : c;
            float acc = 0.f;
#pragma unroll
            for (int h = 0; h < HH; h++) acc = fmaf(g_pooled[g * HH + h], Wr[h], acc);
            out[g] = acc / c + br[0];
        }
        return;
    }
    long t = (long)blockIdx.x * 256 + threadIdx.x;
    int e = (int)(t >> 2), lane = (int)(t & 3);
    if (e >= EAA) return;
    int s = asrc[e], d = adst[e];
    const float4* u4 = reinterpret_cast<const float4*>(g_u);
    const float4* h4 = reinterpret_cast<const float4*>(g_h);
    float4 a0 = u4[s * 8 + lane];
    float4 b0 = h4[d * 8 + lane];
    float4 a1 = u4[s * 8 + lane + 4];
    float4 b1 = h4[d * 8 + lane + 4];
    float p = a0.x*b0.x + a0.y*b0.y + a0.z*b0.z + a0.w*b0.w
            + a1.x*b1.x + a1.y*b1.y + a1.z*b1.z + a1.w*b1.w;
    p += __shfl_down_sync(0xffffffffu, p, 2, 4);
    p += __shfl_down_sync(0xffffffffu, p, 1, 4);
    if (lane == 0) out[GG + e] = p + bbil[0];
}

// ---------------- launch ----------------

extern "C" void kernel_launch(void* const* d_in, const int* in_sizes, int n_in,
                              void* d_out, int out_size) {
    const float* x    = (const float*)d_in[0];
    const int*   ei   = (const int*)  d_in[1];
    const int*   eia  = (const int*)  d_in[2];
    const int*   batch= (const int*)  d_in[3];
    const float* W1   = (const float*)d_in[4];
    const float* b1   = (const float*)d_in[5];
    const float* W2   = (const float*)d_in[6];
    const float* b2   = (const float*)d_in[7];
    const float* Wr   = (const float*)d_in[8];
    const float* br   = (const float*)d_in[9];
    const float* Wbil = (const float*)d_in[10];
    const float* bbil = (const float*)d_in[11];
    float* out = (float*)d_out;

    const int* src  = ei;
    const int* dst  = ei + EE;
    const int* asrc = eia;
    const int* adst = eia + EAA;

    const int B = 256;

    // one-pass slot build (round-10 proven)
    k_zero    <<<(NN + B - 1) / B, B>>>();
    k_fillslot<<<(EE + B - 1) / B, B>>>(src, dst);
    k_dinv    <<<(NN + B - 1) / B, B>>>();

    // layer 1 matmul, then fused gather+relu+layer2 matmul (y1 -> y2)
    k_mm1  <<<(NN * 4 + B - 1) / B, B>>>(x, W1);
    k_gmm  <<<(NN + NODES_PER_BLK - 1) / NODES_PER_BLK, B>>>(b1, W2);

    // fused gather(y2) + epilogue + pooling + bilinear precompute
    k_ghead<<<(NN + NODES_PER_BLK - 1) / NODES_PER_BLK, B>>>(b2, Wbil, batch);

    // edge head + fused reg head
    int edge_blocks = (int)(((long)EAA * 4 + B - 1) / B);
    k_edge <<<edge_blocks + 1, B>>>(asrc, adst, bbil, Wr, br, out);
}

// round 15
// speedup vs baseline: 1.2907x; 1.0571x over previous
#include <cuda_runtime.h>

#define NN   100000
#define EE   1600000
#define EAA  1000000
#define GG   512
#define F_INN 16
#define HH   32
#define SLOTS 96

// ---- scratch (device globals) ----
__device__ __align__(16) float g_deg[NN];          // dinv
__device__ __align__(16) float g_y  [NN * HH];     // layer-1 gather source (y1)
__device__ __align__(16) float g_y2 [NN * HH];     // layer-2 gather source (y2)
__device__ __align__(16) float g_h  [NN * HH];     // layer-2 output (edge head)
__device__ __align__(16) float g_u  [NN * HH];     // h @ Wbil
__device__ __align__(16) float g_pooled[GG * HH];
__device__ float g_cnt[GG];
__device__ int   g_cnt_i[NN];                      // in-degree (no self loop)
__device__ int   g_slot[NN * SLOTS];               // src ids, fixed stride per dst

// ---------------- build kernels (round-10 proven) ----------------

__global__ void k_zero() {
    int i = blockIdx.x * blockDim.x + threadIdx.x;
    if (i < NN)      g_cnt_i[i] = 0;
    if (i < GG * HH) g_pooled[i] = 0.f;
    if (i < GG)      g_cnt[i] = 0.f;
}

__global__ void k_fillslot(const int* __restrict__ src, const int* __restrict__ dst) {
    int e = blockIdx.x * blockDim.x + threadIdx.x;
    if (e >= EE) return;
    int d = dst[e];
    int slot = atomicAdd(&g_cnt_i[d], 1);
    g_slot[d * SLOTS + slot] = src[e];
}

__global__ void k_dinv() {
    int i = blockIdx.x * blockDim.x + threadIdx.x;
    if (i < NN) g_deg[i] = rsqrtf((float)g_cnt_i[i] + 1.0f);
}

// ---------------- compute kernels ----------------

// y1 = (x @ W1) * dinv ; 4 threads per node (round-10 proven)
__global__ void k_mm1(const float* __restrict__ x, const float* __restrict__ W1) {
    __shared__ float sW[F_INN * HH];
    for (int i = threadIdx.x; i < F_INN * HH; i += blockDim.x) sW[i] = W1[i];
    __syncthreads();
    int t = blockIdx.x * blockDim.x + threadIdx.x;
    int node = t >> 2, q = t & 3;
    if (node >= NN) return;
    float acc[8];
#pragma unroll
    for (int j = 0; j < 8; j++) acc[j] = 0.f;
    const float4* xr = reinterpret_cast<const float4*>(x + node * F_INN);
#pragma unroll
    for (int kk = 0; kk < F_INN / 4; kk++) {
        float4 xv = xr[kk];
        float xs[4] = {xv.x, xv.y, xv.z, xv.w};
#pragma unroll
        for (int p = 0; p < 4; p++) {
            int k = kk * 4 + p;
#pragma unroll
            for (int j = 0; j < 8; j++)
                acc[j] = fmaf(xs[p], sW[k * HH + q * 8 + j], acc[j]);
        }
    }
    float dv = g_deg[node];
    int o = node * 8 + q * 2;
    reinterpret_cast<float4*>(g_y)[o]     = make_float4(acc[0]*dv, acc[1]*dv, acc[2]*dv, acc[3]*dv);
    reinterpret_cast<float4*>(g_y)[o + 1] = make_float4(acc[4]*dv, acc[5]*dv, acc[6]*dv, acc[7]*dv);
}

// gather helper (round-10 proven): unroll 2, scalar index loads
__device__ __forceinline__ float4 gather_rows(const float4* __restrict__ y4,
                                              int base, int m, int c, float4 acc) {
    int i = 0;
    for (; i + 2 <= m; i += 2) {
        int s0 = g_slot[base + i];
        int s1 = g_slot[base + i + 1];
        float4 v0 = y4[s0 * 8 + c];
        float4 v1 = y4[s1 * 8 + c];
        acc.x += v0.x + v1.x; acc.y += v0.y + v1.y;
        acc.z += v0.z + v1.z; acc.w += v0.w + v1.w;
    }
    if (i < m) {
        float4 v = y4[g_slot[base + i] * 8 + c];
        acc.x += v.x; acc.y += v.y; acc.z += v.z; acc.w += v.w;
    }
    return acc;
}

// fused: slot gather of y1 + relu epilogue (smem) + @W2 matmul -> y2 (*dinv)
#define NODES_PER_BLK 32
#define HPAD 36
__global__ void k_gmm(const float* __restrict__ b1, const float* __restrict__ W2) {
    __shared__ float sW[HH * HH];
    __shared__ float sb[HH];
    __shared__ float sh[NODES_PER_BLK * HPAD];
    for (int i = threadIdx.x; i < HH * HH; i += blockDim.x) sW[i] = W2[i];
    if (threadIdx.x < HH) sb[threadIdx.x] = b1[threadIdx.x];
    __syncthreads();

    int tid = threadIdx.x;
    int nl = tid >> 3, c = tid & 7;
    int node = blockIdx.x * NODES_PER_BLK + nl;
    bool ok = node < NN;

    if (ok) {
        int base = node * SLOTS;
        int m    = g_cnt_i[node];
        const float4* y4 = reinterpret_cast<const float4*>(g_y);
        float4 acc = gather_rows(y4, base, m, c, y4[node * 8 + c]);
        float dv = g_deg[node];
        float* hr = sh + nl * HPAD + c * 4;
        hr[0] = fmaxf(acc.x * dv + sb[c*4+0], 0.f);
        hr[1] = fmaxf(acc.y * dv + sb[c*4+1], 0.f);
        hr[2] = fmaxf(acc.z * dv + sb[c*4+2], 0.f);
        hr[3] = fmaxf(acc.w * dv + sb[c*4+3], 0.f);
    }
    __syncthreads();
    if (!ok) return;

    float a0 = 0.f, a1 = 0.f, a2 = 0.f, a3 = 0.f;
    const float* hrow = sh + nl * HPAD;
#pragma unroll
    for (int k = 0; k < HH; k++) {
        float hv = hrow[k];
        a0 = fmaf(hv, sW[k * HH + c * 4 + 0], a0);
        a1 = fmaf(hv, sW[k * HH + c * 4 + 1], a1);
        a2 = fmaf(hv, sW[k * HH + c * 4 + 2], a2);
        a3 = fmaf(hv, sW[k * HH + c * 4 + 3], a3);
    }
    float dv = g_deg[node];
    reinterpret_cast<float4*>(g_y2)[node * 8 + c] =
        make_float4(a0 * dv, a1 * dv, a2 * dv, a3 * dv);
}

// fused: slot gather of y2 + epilogue -> g_h, RUN-LENGTH pooling, u = h2 @ Wbil
__global__ void k_ghead(const float* __restrict__ b2, const float* __restrict__ Wbil,
                        const int* __restrict__ batch) {
    __shared__ float sW[HH * HH];
    __shared__ float sb[HH];
    __shared__ float sh[NODES_PER_BLK * HPAD];
    __shared__ int   sbatch[NODES_PER_BLK];
    for (int i = threadIdx.x; i < HH * HH; i += blockDim.x) sW[i] = Wbil[i];
    if (threadIdx.x < HH) sb[threadIdx.x] = b2[threadIdx.x];
    __syncthreads();

    int tid = threadIdx.x;
    int nl = tid >> 3, c = tid & 7;
    int node = blockIdx.x * NODES_PER_BLK + nl;
    bool ok = node < NN;

    int g = ok ? batch[node] : -1;
    if (c == 0) sbatch[nl] = g;

    if (ok) {
        int base = node * SLOTS;
        int m    = g_cnt_i[node];
        const float4* y4 = reinterpret_cast<const float4*>(g_y2);
        float4 acc = gather_rows(y4, base, m, c, y4[node * 8 + c]);
        float dv = g_deg[node];
        float4 h2;
        h2.x = acc.x * dv + sb[c*4+0];
        h2.y = acc.y * dv + sb[c*4+1];
        h2.z = acc.z * dv + sb[c*4+2];
        h2.w = acc.w * dv + sb[c*4+3];
        float* hr = sh + nl * HPAD + c * 4;
        hr[0] = h2.x; hr[1] = h2.y; hr[2] = h2.z; hr[3] = h2.w;
        reinterpret_cast<float4*>(g_h)[node * 8 + c] = h2;
    }
    __syncthreads();

    // run-length pooling: batch is sorted, so block nodes form few runs.
    // The last thread of each run sums the run's sh rows and does ONE atomic.
    if (ok) {
        bool is_last = (nl == NODES_PER_BLK - 1) || (sbatch[nl + 1] != g);
        if (is_last) {
            float4 acc = make_float4(0.f, 0.f, 0.f, 0.f);
            int j = nl, runlen = 0;
            while (j >= 0 && sbatch[j] == g) {
                const float* hr = sh + j * HPAD + c * 4;
                acc.x += hr[0]; acc.y += hr[1]; acc.z += hr[2]; acc.w += hr[3];
                runlen++; j--;
            }
            atomicAdd(reinterpret_cast<float4*>(g_pooled) + g * 8 + c, acc);
            if (c == 0) atomicAdd(&g_cnt[g], (float)runlen);
        }
    }
    if (!ok) return;

    float a0 = 0.f, a1 = 0.f, a2 = 0.f, a3 = 0.f;
    const float* hrow = sh + nl * HPAD;
#pragma unroll
    for (int k = 0; k < HH; k++) {
        float hv = hrow[k];
        a0 = fmaf(hv, sW[k * HH + c * 4 + 0], a0);
        a1 = fmaf(hv, sW[k * HH + c * 4 + 1], a1);
        a2 = fmaf(hv, sW[k * HH + c * 4 + 2], a2);
        a3 = fmaf(hv, sW[k * HH + c * 4 + 3], a3);
    }
    reinterpret_cast<float4*>(g_u)[node * 8 + c] = make_float4(a0, a1, a2, a3);
}

// edge head (4 threads/edge, 2x float4 per operand) + fused reg head in last block
__global__ void k_edge(const int* __restrict__ asrc, const int* __restrict__ adst,
                       const float* __restrict__ bbil,
                       const float* __restrict__ Wr, const float* __restrict__ br,
                       float* __restrict__ out) {
    if (blockIdx.x == gridDim.x - 1) {
        for (int g = threadIdx.x; g < GG; g += 256) {
            float c = g_cnt[g];
            c = c < 1.f ? 1.f : c;
            float acc = 0.f;
#pragma unroll
            for (int h = 0; h < HH; h++) acc = fmaf(g_pooled[g * HH + h], Wr[h], acc);
            out[g] = acc / c + br[0];
        }
        return;
    }
    long t = (long)blockIdx.x * 256 + threadIdx.x;
    int e = (int)(t >> 2), lane = (int)(t & 3);
    if (e >= EAA) return;
    int s = asrc[e], d = adst[e];
    const float4* u4 = reinterpret_cast<const float4*>(g_u);
    const float4* h4 = reinterpret_cast<const float4*>(g_h);
    float4 a0 = u4[s * 8 + lane];
    float4 b0 = h4[d * 8 + lane];
    float4 a1 = u4[s * 8 + lane + 4];
    float4 b1 = h4[d * 8 + lane + 4];
    float p = a0.x*b0.x + a0.y*b0.y + a0.z*b0.z + a0.w*b0.w
            + a1.x*b1.x + a1.y*b1.y + a1.z*b1.z + a1.w*b1.w;
    p += __shfl_down_sync(0xffffffffu, p, 2, 4);
    p += __shfl_down_sync(0xffffffffu, p, 1, 4);
    if (lane == 0) out[GG + e] = p + bbil[0];
}

// ---------------- launch ----------------

extern "C" void kernel_launch(void* const* d_in, const int* in_sizes, int n_in,
                              void* d_out, int out_size) {
    const float* x    = (const float*)d_in[0];
    const int*   ei   = (const int*)  d_in[1];
    const int*   eia  = (const int*)  d_in[2];
    const int*   batch= (const int*)  d_in[3];
    const float* W1   = (const float*)d_in[4];
    const float* b1   = (const float*)d_in[5];
    const float* W2   = (const float*)d_in[6];
    const float* b2   = (const float*)d_in[7];
    const float* Wr   = (const float*)d_in[8];
    const float* br   = (const float*)d_in[9];
    const float* Wbil = (const float*)d_in[10];
    const float* bbil = (const float*)d_in[11];
    float* out = (float*)d_out;

    const int* src  = ei;
    const int* dst  = ei + EE;
    const int* asrc = eia;
    const int* adst = eia + EAA;

    const int B = 256;

    // one-pass slot build (round-10 proven)
    k_zero    <<<(NN + B - 1) / B, B>>>();
    k_fillslot<<<(EE + B - 1) / B, B>>>(src, dst);
    k_dinv    <<<(NN + B - 1) / B, B>>>();

    // layer 1 matmul, then fused gather+relu+layer2 matmul (y1 -> y2)
    k_mm1  <<<(NN * 4 + B - 1) / B, B>>>(x, W1);
    k_gmm  <<<(NN + NODES_PER_BLK - 1) / NODES_PER_BLK, B>>>(b1, W2);

    // fused gather(y2) + epilogue + run-length pooling + bilinear precompute
    k_ghead<<<(NN + NODES_PER_BLK - 1) / NODES_PER_BLK, B>>>(b2, Wbil, batch);

    // edge head + fused reg head
    int edge_blocks = (int)(((long)EAA * 4 + B - 1) / B);
    k_edge <<<edge_blocks + 1, B>>>(asrc, adst, bbil, Wr, br, out);
}

// round 16
// speedup vs baseline: 1.3439x; 1.0412x over previous
#include <cuda_runtime.h>
#include <cuda_fp16.h>

#define NN   100000
#define EE   1600000
#define EAA  1000000
#define GG   512
#define F_INN 16
#define HH   32
#define SLOTS 96

// ---- scratch (device globals) ----
__device__ __align__(16) float g_deg[NN];          // dinv
__device__ __align__(16) float g_y  [NN * HH];     // layer-1 gather source (y1)
__device__ __align__(16) float g_y2 [NN * HH];     // layer-2 gather source (y2)
__device__ __align__(16) __half2 g_h16[NN * 16];   // layer-2 output, fp16 (edge head)
__device__ __align__(16) __half2 g_u16[NN * 16];   // h @ Wbil, fp16 (edge head)
__device__ __align__(16) float g_pooled[GG * HH];
__device__ float g_cnt[GG];
__device__ int   g_cnt_i[NN];                      // in-degree (no self loop)
__device__ int   g_slot[NN * SLOTS];               // src ids, fixed stride per dst

// ---------------- build kernels (round-10 proven) ----------------

__global__ void k_zero() {
    int i = blockIdx.x * blockDim.x + threadIdx.x;
    if (i < NN)      g_cnt_i[i] = 0;
    if (i < GG * HH) g_pooled[i] = 0.f;
    if (i < GG)      g_cnt[i] = 0.f;
}

__global__ void k_fillslot(const int* __restrict__ src, const int* __restrict__ dst) {
    int e = blockIdx.x * blockDim.x + threadIdx.x;
    if (e >= EE) return;
    int d = dst[e];
    int slot = atomicAdd(&g_cnt_i[d], 1);
    g_slot[d * SLOTS + slot] = src[e];
}

__global__ void k_dinv() {
    int i = blockIdx.x * blockDim.x + threadIdx.x;
    if (i < NN) g_deg[i] = rsqrtf((float)g_cnt_i[i] + 1.0f);
}

// ---------------- compute kernels ----------------

// y1 = (x @ W1) * dinv ; 4 threads per node (round-10 proven)
__global__ void k_mm1(const float* __restrict__ x, const float* __restrict__ W1) {
    __shared__ float sW[F_INN * HH];
    for (int i = threadIdx.x; i < F_INN * HH; i += blockDim.x) sW[i] = W1[i];
    __syncthreads();
    int t = blockIdx.x * blockDim.x + threadIdx.x;
    int node = t >> 2, q = t & 3;
    if (node >= NN) return;
    float acc[8];
#pragma unroll
    for (int j = 0; j < 8; j++) acc[j] = 0.f;
    const float4* xr = reinterpret_cast<const float4*>(x + node * F_INN);
#pragma unroll
    for (int kk = 0; kk < F_INN / 4; kk++) {
        float4 xv = xr[kk];
        float xs[4] = {xv.x, xv.y, xv.z, xv.w};
#pragma unroll
        for (int p = 0; p < 4; p++) {
            int k = kk * 4 + p;
#pragma unroll
            for (int j = 0; j < 8; j++)
                acc[j] = fmaf(xs[p], sW[k * HH + q * 8 + j], acc[j]);
        }
    }
    float dv = g_deg[node];
    int o = node * 8 + q * 2;
    reinterpret_cast<float4*>(g_y)[o]     = make_float4(acc[0]*dv, acc[1]*dv, acc[2]*dv, acc[3]*dv);
    reinterpret_cast<float4*>(g_y)[o + 1] = make_float4(acc[4]*dv, acc[5]*dv, acc[6]*dv, acc[7]*dv);
}

// gather helper (round-10 proven): unroll 2, scalar index loads
__device__ __forceinline__ float4 gather_rows(const float4* __restrict__ y4,
                                              int base, int m, int c, float4 acc) {
    int i = 0;
    for (; i + 2 <= m; i += 2) {
        int s0 = g_slot[base + i];
        int s1 = g_slot[base + i + 1];
        float4 v0 = y4[s0 * 8 + c];
        float4 v1 = y4[s1 * 8 + c];
        acc.x += v0.x + v1.x; acc.y += v0.y + v1.y;
        acc.z += v0.z + v1.z; acc.w += v0.w + v1.w;
    }
    if (i < m) {
        float4 v = y4[g_slot[base + i] * 8 + c];
        acc.x += v.x; acc.y += v.y; acc.z += v.z; acc.w += v.w;
    }
    return acc;
}

// fused: slot gather of y1 + relu epilogue (smem) + @W2 matmul -> y2 (*dinv)
#define NODES_PER_BLK 32
#define HPAD 36
__global__ void k_gmm(const float* __restrict__ b1, const float* __restrict__ W2) {
    __shared__ float sW[HH * HH];
    __shared__ float sb[HH];
    __shared__ float sh[NODES_PER_BLK * HPAD];
    for (int i = threadIdx.x; i < HH * HH; i += blockDim.x) sW[i] = W2[i];
    if (threadIdx.x < HH) sb[threadIdx.x] = b1[threadIdx.x];
    __syncthreads();

    int tid = threadIdx.x;
    int nl = tid >> 3, c = tid & 7;
    int node = blockIdx.x * NODES_PER_BLK + nl;
    bool ok = node < NN;

    if (ok) {
        int base = node * SLOTS;
        int m    = g_cnt_i[node];
        const float4* y4 = reinterpret_cast<const float4*>(g_y);
        float4 acc = gather_rows(y4, base, m, c, y4[node * 8 + c]);
        float dv = g_deg[node];
        float* hr = sh + nl * HPAD + c * 4;
        hr[0] = fmaxf(acc.x * dv + sb[c*4+0], 0.f);
        hr[1] = fmaxf(acc.y * dv + sb[c*4+1], 0.f);
        hr[2] = fmaxf(acc.z * dv + sb[c*4+2], 0.f);
        hr[3] = fmaxf(acc.w * dv + sb[c*4+3], 0.f);
    }
    __syncthreads();
    if (!ok) return;

    float a0 = 0.f, a1 = 0.f, a2 = 0.f, a3 = 0.f;
    const float* hrow = sh + nl * HPAD;
#pragma unroll
    for (int k = 0; k < HH; k++) {
        float hv = hrow[k];
        a0 = fmaf(hv, sW[k * HH + c * 4 + 0], a0);
        a1 = fmaf(hv, sW[k * HH + c * 4 + 1], a1);
        a2 = fmaf(hv, sW[k * HH + c * 4 + 2], a2);
        a3 = fmaf(hv, sW[k * HH + c * 4 + 3], a3);
    }
    float dv = g_deg[node];
    reinterpret_cast<float4*>(g_y2)[node * 8 + c] =
        make_float4(a0 * dv, a1 * dv, a2 * dv, a3 * dv);
}

// fused: slot gather of y2 + epilogue -> g_h16 (fp16), run-length pooling,
// u = h2 @ Wbil -> g_u16 (fp16)
__global__ void k_ghead(const float* __restrict__ b2, const float* __restrict__ Wbil,
                        const int* __restrict__ batch) {
    __shared__ float sW[HH * HH];
    __shared__ float sb[HH];
    __shared__ float sh[NODES_PER_BLK * HPAD];
    __shared__ int   sbatch[NODES_PER_BLK];
    for (int i = threadIdx.x; i < HH * HH; i += blockDim.x) sW[i] = Wbil[i];
    if (threadIdx.x < HH) sb[threadIdx.x] = b2[threadIdx.x];
    __syncthreads();

    int tid = threadIdx.x;
    int nl = tid >> 3, c = tid & 7;
    int node = blockIdx.x * NODES_PER_BLK + nl;
    bool ok = node < NN;

    int g = ok ? batch[node] : -1;
    if (c == 0) sbatch[nl] = g;

    if (ok) {
        int base = node * SLOTS;
        int m    = g_cnt_i[node];
        const float4* y4 = reinterpret_cast<const float4*>(g_y2);
        float4 acc = gather_rows(y4, base, m, c, y4[node * 8 + c]);
        float dv = g_deg[node];
        float4 h2;
        h2.x = acc.x * dv + sb[c*4+0];
        h2.y = acc.y * dv + sb[c*4+1];
        h2.z = acc.z * dv + sb[c*4+2];
        h2.w = acc.w * dv + sb[c*4+3];
        float* hr = sh + nl * HPAD + c * 4;
        hr[0] = h2.x; hr[1] = h2.y; hr[2] = h2.z; hr[3] = h2.w;
        __half2* hp = g_h16 + node * 16 + c * 2;
        hp[0] = __floats2half2_rn(h2.x, h2.y);
        hp[1] = __floats2half2_rn(h2.z, h2.w);
    }
    __syncthreads();

    // run-length pooling: batch is sorted; one atomic per (run, chunk)
    if (ok) {
        bool is_last = (nl == NODES_PER_BLK - 1) || (sbatch[nl + 1] != g);
        if (is_last) {
            float4 acc = make_float4(0.f, 0.f, 0.f, 0.f);
            int j = nl, runlen = 0;
            while (j >= 0 && sbatch[j] == g) {
                const float* hr = sh + j * HPAD + c * 4;
                acc.x += hr[0]; acc.y += hr[1]; acc.z += hr[2]; acc.w += hr[3];
                runlen++; j--;
            }
            atomicAdd(reinterpret_cast<float4*>(g_pooled) + g * 8 + c, acc);
            if (c == 0) atomicAdd(&g_cnt[g], (float)runlen);
        }
    }
    if (!ok) return;

    float a0 = 0.f, a1 = 0.f, a2 = 0.f, a3 = 0.f;
    const float* hrow = sh + nl * HPAD;
#pragma unroll
    for (int k = 0; k < HH; k++) {
        float hv = hrow[k];
        a0 = fmaf(hv, sW[k * HH + c * 4 + 0], a0);
        a1 = fmaf(hv, sW[k * HH + c * 4 + 1], a1);
        a2 = fmaf(hv, sW[k * HH + c * 4 + 2], a2);
        a3 = fmaf(hv, sW[k * HH + c * 4 + 3], a3);
    }
    __half2* up = g_u16 + node * 16 + c * 2;
    up[0] = __floats2half2_rn(a0, a1);
    up[1] = __floats2half2_rn(a2, a3);
}

// fp16 dot fragment: 8 halves per uint4 word-pair
__device__ __forceinline__ float dot8_h16(uint4 a, uint4 b) {
    float p = 0.f;
    const unsigned* aw = &a.x;
    const unsigned* bw = &b.x;
#pragma unroll
    for (int w = 0; w < 4; w++) {
        float2 fa = __half22float2(*reinterpret_cast<const __half2*>(&aw[w]));
        float2 fb = __half22float2(*reinterpret_cast<const __half2*>(&bw[w]));
        p = fmaf(fa.x, fb.x, p);
        p = fmaf(fa.y, fb.y, p);
    }
    return p;
}

// edge head (4 threads/edge, fp16 rows) + fused reg head in last block
__global__ void k_edge(const int* __restrict__ asrc, const int* __restrict__ adst,
                       const float* __restrict__ bbil,
                       const float* __restrict__ Wr, const float* __restrict__ br,
                       float* __restrict__ out) {
    if (blockIdx.x == gridDim.x - 1) {
        for (int g = threadIdx.x; g < GG; g += 256) {
            float c = g_cnt[g];
            c = c < 1.f ? 1.f : c;
            float acc = 0.f;
#pragma unroll
            for (int h = 0; h < HH; h++) acc = fmaf(g_pooled[g * HH + h], Wr[h], acc);
            out[g] = acc / c + br[0];
        }
        return;
    }
    long t = (long)blockIdx.x * 256 + threadIdx.x;
    int e = (int)(t >> 2), lane = (int)(t & 3);
    if (e >= EAA) return;
    int s = asrc[e], d = adst[e];
    const uint4* u16 = reinterpret_cast<const uint4*>(g_u16);   // 16B = 8 halves
    const uint4* h16 = reinterpret_cast<const uint4*>(g_h16);
    uint4 a = u16[s * 4 + lane];   // row = 64B = 4 uint4
    uint4 b = h16[d * 4 + lane];
    float p = dot8_h16(a, b);
    p += __shfl_down_sync(0xffffffffu, p, 2, 4);
    p += __shfl_down_sync(0xffffffffu, p, 1, 4);
    if (lane == 0) out[GG + e] = p + bbil[0];
}

// ---------------- launch ----------------

extern "C" void kernel_launch(void* const* d_in, const int* in_sizes, int n_in,
                              void* d_out, int out_size) {
    const float* x    = (const float*)d_in[0];
    const int*   ei   = (const int*)  d_in[1];
    const int*   eia  = (const int*)  d_in[2];
    const int*   batch= (const int*)  d_in[3];
    const float* W1   = (const float*)d_in[4];
    const float* b1   = (const float*)d_in[5];
    const float* W2   = (const float*)d_in[6];
    const float* b2   = (const float*)d_in[7];
    const float* Wr   = (const float*)d_in[8];
    const float* br   = (const float*)d_in[9];
    const float* Wbil = (const float*)d_in[10];
    const float* bbil = (const float*)d_in[11];
    float* out = (float*)d_out;

    const int* src  = ei;
    const int* dst  = ei + EE;
    const int* asrc = eia;
    const int* adst = eia + EAA;

    const int B = 256;

    // one-pass slot build (round-10 proven)
    k_zero    <<<(NN + B - 1) / B, B>>>();
    k_fillslot<<<(EE + B - 1) / B, B>>>(src, dst);
    k_dinv    <<<(NN + B - 1) / B, B>>>();

    // layer 1 matmul, then fused gather+relu+layer2 matmul (y1 -> y2)
    k_mm1  <<<(NN * 4 + B - 1) / B, B>>>(x, W1);
    k_gmm  <<<(NN + NODES_PER_BLK - 1) / NODES_PER_BLK, B>>>(b1, W2);

    // fused gather(y2) + epilogue + pooling + bilinear precompute (fp16 out)
    k_ghead<<<(NN + NODES_PER_BLK - 1) / NODES_PER_BLK, B>>>(b2, Wbil, batch);

    // edge head (fp16 operands) + fused reg head
    int edge_blocks = (int)(((long)EAA * 4 + B - 1) / B);
    k_edge <<<edge_blocks + 1, B>>>(asrc, adst, bbil, Wr, br, out);
}

// round 17
// speedup vs baseline: 1.3661x; 1.0165x over previous
#include <cuda_runtime.h>
#include <cuda_fp16.h>

#define NN   100000
#define EE   1600000
#define EAA  1000000
#define GG   512
#define F_INN 16
#define HH   32
#define SLOTS 96

// ---- scratch (device globals) ----
__device__ __align__(16) float g_deg[NN];          // dinv
__device__ __align__(16) float g_y  [NN * HH];     // layer-1 gather source (y1)
__device__ __align__(16) float g_y2 [NN * HH];     // layer-2 gather source (y2)
__device__ __align__(16) __half2 g_h16[NN * 16];   // layer-2 output, fp16 (edge head)
__device__ __align__(16) __half2 g_u16[NN * 16];   // h @ Wbil, fp16 (edge head)
__device__ __align__(16) float g_pooled[GG * HH];
__device__ float g_cnt[GG];
__device__ int   g_cnt_i[NN];                      // in-degree (no self loop)
__device__ int   g_slot[NN * SLOTS];               // src ids, fixed stride per dst

// ---------------- build kernels ----------------

__global__ void k_zero() {
    int i = blockIdx.x * blockDim.x + threadIdx.x;
    if (i < NN)      g_cnt_i[i] = 0;
    if (i < GG * HH) g_pooled[i] = 0.f;
    if (i < GG)      g_cnt[i] = 0.f;
}

__global__ void k_fillslot(const int* __restrict__ src, const int* __restrict__ dst) {
    int e = blockIdx.x * blockDim.x + threadIdx.x;
    if (e >= EE) return;
    int d = dst[e];
    int slot = atomicAdd(&g_cnt_i[d], 1);
    g_slot[d * SLOTS + slot] = src[e];
}

// ---------------- compute kernels ----------------

// y1 = (x @ W1) * dinv ; 4 threads per node ; dinv computed inline (fused k_dinv)
__global__ void k_mm1(const float* __restrict__ x, const float* __restrict__ W1) {
    __shared__ float sW[F_INN * HH];
    for (int i = threadIdx.x; i < F_INN * HH; i += blockDim.x) sW[i] = W1[i];
    __syncthreads();
    int t = blockIdx.x * blockDim.x + threadIdx.x;
    int node = t >> 2, q = t & 3;
    if (node >= NN) return;
    float acc[8];
#pragma unroll
    for (int j = 0; j < 8; j++) acc[j] = 0.f;
    const float4* xr = reinterpret_cast<const float4*>(x + node * F_INN);
#pragma unroll
    for (int kk = 0; kk < F_INN / 4; kk++) {
        float4 xv = xr[kk];
        float xs[4] = {xv.x, xv.y, xv.z, xv.w};
#pragma unroll
        for (int p = 0; p < 4; p++) {
            int k = kk * 4 + p;
#pragma unroll
            for (int j = 0; j < 8; j++)
                acc[j] = fmaf(xs[p], sW[k * HH + q * 8 + j], acc[j]);
        }
    }
    float dv = rsqrtf((float)g_cnt_i[node] + 1.0f);   // fused dinv
    if (q == 0) g_deg[node] = dv;
    int o = node * 8 + q * 2;
    reinterpret_cast<float4*>(g_y)[o]     = make_float4(acc[0]*dv, acc[1]*dv, acc[2]*dv, acc[3]*dv);
    reinterpret_cast<float4*>(g_y)[o + 1] = make_float4(acc[4]*dv, acc[5]*dv, acc[6]*dv, acc[7]*dv);
}

// gather helper (round-10 proven): unroll 2, scalar index loads
__device__ __forceinline__ float4 gather_rows(const float4* __restrict__ y4,
                                              int base, int m, int c, float4 acc) {
    int i = 0;
    for (; i + 2 <= m; i += 2) {
        int s0 = g_slot[base + i];
        int s1 = g_slot[base + i + 1];
        float4 v0 = y4[s0 * 8 + c];
        float4 v1 = y4[s1 * 8 + c];
        acc.x += v0.x + v1.x; acc.y += v0.y + v1.y;
        acc.z += v0.z + v1.z; acc.w += v0.w + v1.w;
    }
    if (i < m) {
        float4 v = y4[g_slot[base + i] * 8 + c];
        acc.x += v.x; acc.y += v.y; acc.z += v.z; acc.w += v.w;
    }
    return acc;
}

// fused: slot gather of y1 + relu epilogue (smem) + @W2 matmul -> y2 (*dinv)
#define NODES_PER_BLK 32
#define HPAD 36
__global__ void k_gmm(const float* __restrict__ b1, const float* __restrict__ W2) {
    __shared__ float sW[HH * HH];
    __shared__ float sb[HH];
    __shared__ float sh[NODES_PER_BLK * HPAD];
    for (int i = threadIdx.x; i < HH * HH; i += blockDim.x) sW[i] = W2[i];
    if (threadIdx.x < HH) sb[threadIdx.x] = b1[threadIdx.x];
    __syncthreads();

    int tid = threadIdx.x;
    int nl = tid >> 3, c = tid & 7;
    int node = blockIdx.x * NODES_PER_BLK + nl;
    bool ok = node < NN;

    if (ok) {
        int base = node * SLOTS;
        int m    = g_cnt_i[node];
        const float4* y4 = reinterpret_cast<const float4*>(g_y);
        float4 acc = gather_rows(y4, base, m, c, y4[node * 8 + c]);
        float dv = g_deg[node];
        float* hr = sh + nl * HPAD + c * 4;
        hr[0] = fmaxf(acc.x * dv + sb[c*4+0], 0.f);
        hr[1] = fmaxf(acc.y * dv + sb[c*4+1], 0.f);
        hr[2] = fmaxf(acc.z * dv + sb[c*4+2], 0.f);
        hr[3] = fmaxf(acc.w * dv + sb[c*4+3], 0.f);
    }
    __syncthreads();
    if (!ok) return;

    float a0 = 0.f, a1 = 0.f, a2 = 0.f, a3 = 0.f;
    const float* hrow = sh + nl * HPAD;
#pragma unroll
    for (int k = 0; k < HH; k++) {
        float hv = hrow[k];
        a0 = fmaf(hv, sW[k * HH + c * 4 + 0], a0);
        a1 = fmaf(hv, sW[k * HH + c * 4 + 1], a1);
        a2 = fmaf(hv, sW[k * HH + c * 4 + 2], a2);
        a3 = fmaf(hv, sW[k * HH + c * 4 + 3], a3);
    }
    float dv = g_deg[node];
    reinterpret_cast<float4*>(g_y2)[node * 8 + c] =
        make_float4(a0 * dv, a1 * dv, a2 * dv, a3 * dv);
}

// fused: slot gather of y2 + epilogue -> g_h16 (fp16), run-length pooling,
// u = h2 @ Wbil -> g_u16 (fp16)
__global__ void k_ghead(const float* __restrict__ b2, const float* __restrict__ Wbil,
                        const int* __restrict__ batch) {
    __shared__ float sW[HH * HH];
    __shared__ float sb[HH];
    __shared__ float sh[NODES_PER_BLK * HPAD];
    __shared__ int   sbatch[NODES_PER_BLK];
    for (int i = threadIdx.x; i < HH * HH; i += blockDim.x) sW[i] = Wbil[i];
    if (threadIdx.x < HH) sb[threadIdx.x] = b2[threadIdx.x];
    __syncthreads();

    int tid = threadIdx.x;
    int nl = tid >> 3, c = tid & 7;
    int node = blockIdx.x * NODES_PER_BLK + nl;
    bool ok = node < NN;

    int g = ok ? batch[node] : -1;
    if (c == 0) sbatch[nl] = g;

    if (ok) {
        int base = node * SLOTS;
        int m    = g_cnt_i[node];
        const float4* y4 = reinterpret_cast<const float4*>(g_y2);
        float4 acc = gather_rows(y4, base, m, c, y4[node * 8 + c]);
        float dv = g_deg[node];
        float4 h2;
        h2.x = acc.x * dv + sb[c*4+0];
        h2.y = acc.y * dv + sb[c*4+1];
        h2.z = acc.z * dv + sb[c*4+2];
        h2.w = acc.w * dv + sb[c*4+3];
        float* hr = sh + nl * HPAD + c * 4;
        hr[0] = h2.x; hr[1] = h2.y; hr[2] = h2.z; hr[3] = h2.w;
        __half2* hp = g_h16 + node * 16 + c * 2;
        hp[0] = __floats2half2_rn(h2.x, h2.y);
        hp[1] = __floats2half2_rn(h2.z, h2.w);
    }
    __syncthreads();

    // run-length pooling: batch is sorted; one atomic per (run, chunk)
    if (ok) {
        bool is_last = (nl == NODES_PER_BLK - 1) || (sbatch[nl + 1] != g);
        if (is_last) {
            float4 acc = make_float4(0.f, 0.f, 0.f, 0.f);
            int j = nl, runlen = 0;
            while (j >= 0 && sbatch[j] == g) {
                const float* hr = sh + j * HPAD + c * 4;
                acc.x += hr[0]; acc.y += hr[1]; acc.z += hr[2]; acc.w += hr[3];
                runlen++; j--;
            }
            atomicAdd(reinterpret_cast<float4*>(g_pooled) + g * 8 + c, acc);
            if (c == 0) atomicAdd(&g_cnt[g], (float)runlen);
        }
    }
    if (!ok) return;

    float a0 = 0.f, a1 = 0.f, a2 = 0.f, a3 = 0.f;
    const float* hrow = sh + nl * HPAD;
#pragma unroll
    for (int k = 0; k < HH; k++) {
        float hv = hrow[k];
        a0 = fmaf(hv, sW[k * HH + c * 4 + 0], a0);
        a1 = fmaf(hv, sW[k * HH + c * 4 + 1], a1);
        a2 = fmaf(hv, sW[k * HH + c * 4 + 2], a2);
        a3 = fmaf(hv, sW[k * HH + c * 4 + 3], a3);
    }
    __half2* up = g_u16 + node * 16 + c * 2;
    up[0] = __floats2half2_rn(a0, a1);
    up[1] = __floats2half2_rn(a2, a3);
}

// fp16 dot fragment: 8 halves per uint4 word-pair
__device__ __forceinline__ float dot8_h16(uint4 a, uint4 b) {
    float p = 0.f;
    const unsigned* aw = &a.x;
    const unsigned* bw = &b.x;
#pragma unroll
    for (int w = 0; w < 4; w++) {
        float2 fa = __half22float2(*reinterpret_cast<const __half2*>(&aw[w]));
        float2 fb = __half22float2(*reinterpret_cast<const __half2*>(&bw[w]));
        p = fmaf(fa.x, fb.x, p);
        p = fmaf(fa.y, fb.y, p);
    }
    return p;
}

// edge head (4 threads/edge, fp16 rows) + fused reg head in last block
__global__ void k_edge(const int* __restrict__ asrc, const int* __restrict__ adst,
                       const float* __restrict__ bbil,
                       const float* __restrict__ Wr, const float* __restrict__ br,
                       float* __restrict__ out) {
    if (blockIdx.x == gridDim.x - 1) {
        for (int g = threadIdx.x; g < GG; g += 256) {
            float c = g_cnt[g];
            c = c < 1.f ? 1.f : c;
            float acc = 0.f;
#pragma unroll
            for (int h = 0; h < HH; h++) acc = fmaf(g_pooled[g * HH + h], Wr[h], acc);
            out[g] = acc / c + br[0];
        }
        return;
    }
    long t = (long)blockIdx.x * 256 + threadIdx.x;
    int e = (int)(t >> 2), lane = (int)(t & 3);
    if (e >= EAA) return;
    int s = asrc[e], d = adst[e];
    const uint4* u16 = reinterpret_cast<const uint4*>(g_u16);   // 16B = 8 halves
    const uint4* h16 = reinterpret_cast<const uint4*>(g_h16);
    uint4 a = u16[s * 4 + lane];   // row = 64B = 4 uint4
    uint4 b = h16[d * 4 + lane];
    float p = dot8_h16(a, b);
    p += __shfl_down_sync(0xffffffffu, p, 2, 4);
    p += __shfl_down_sync(0xffffffffu, p, 1, 4);
    if (lane == 0) out[GG + e] = p + bbil[0];
}

// ---------------- launch ----------------

extern "C" void kernel_launch(void* const* d_in, const int* in_sizes, int n_in,
                              void* d_out, int out_size) {
    const float* x    = (const float*)d_in[0];
    const int*   ei   = (const int*)  d_in[1];
    const int*   eia  = (const int*)  d_in[2];
    const int*   batch= (const int*)  d_in[3];
    const float* W1   = (const float*)d_in[4];
    const float* b1   = (const float*)d_in[5];
    const float* W2   = (const float*)d_in[6];
    const float* b2   = (const float*)d_in[7];
    const float* Wr   = (const float*)d_in[8];
    const float* br   = (const float*)d_in[9];
    const float* Wbil = (const float*)d_in[10];
    const float* bbil = (const float*)d_in[11];
    float* out = (float*)d_out;

    const int* src  = ei;
    const int* dst  = ei + EE;
    const int* asrc = eia;
    const int* adst = eia + EAA;

    const int B = 256;

    // one-pass slot build
    k_zero    <<<(NN + B - 1) / B, B>>>();
    k_fillslot<<<(EE + B - 1) / B, B>>>(src, dst);

    // layer 1 matmul (dinv fused), then fused gather+relu+layer2 matmul
    k_mm1  <<<(NN * 4 + B - 1) / B, B>>>(x, W1);
    k_gmm  <<<(NN + NODES_PER_BLK - 1) / NODES_PER_BLK, B>>>(b1, W2);

    // fused gather(y2) + epilogue + pooling + bilinear precompute (fp16 out)
    k_ghead<<<(NN + NODES_PER_BLK - 1) / NODES_PER_BLK, B>>>(b2, Wbil, batch);

    // edge head (fp16 operands) + fused reg head
    int edge_blocks = (int)(((long)EAA * 4 + B - 1) / B);
    k_edge <<<edge_blocks + 1, B>>>(asrc, adst, bbil, Wr, br, out);
}